// round 1
// baseline (speedup 1.0000x reference)
#include <cuda_runtime.h>

// Problem constants
#define Bn 8
#define Tn 1024
#define Fn 512
#define Dn 64
#define ROWS (Bn*Tn)       // 8192
#define TC 32              // chunk length
#define NC (Tn/TC)         // 32 chunks

// Scratch (no allocations allowed)
__device__ float g_K[ROWS*Dn];
__device__ float g_Q[ROWS*Dn];
__device__ float g_V[ROWS*Dn];
__device__ float g_S[Bn*NC*Dn*Dn];

__device__ __forceinline__ unsigned long long pack2(float a, float b){
    unsigned long long r;
    asm("mov.b64 %0, {%1, %2};" : "=l"(r) : "f"(a), "f"(b));
    return r;
}
__device__ __forceinline__ void fma2(unsigned long long &d, unsigned long long a, unsigned long long b){
    asm("fma.rn.f32x2 %0, %1, %2, %0;" : "+l"(d) : "l"(a), "l"(b));
}
__device__ __forceinline__ float2 unpack2(unsigned long long v){
    float2 u;
    asm("mov.b64 {%0, %1}, %2;" : "=f"(u.x), "=f"(u.y) : "l"(v));
    return u;
}

// ---------------------------------------------------------------------------
// Kernel A: LayerNorm + 3 projections (K,Q,V) + relu + sum-normalization
// 256 blocks x 192 threads; each block = 32 rows.
// smem: xn packed as float2 row-pairs, layout [f][rp] with stride 17 (pad)
// Thread mapping: cg = tid%48 -> (matrix m = cg/16, col group jg = cg%16, 4 cols)
//                 rg = tid/48 -> 4 row-pairs (8 rows)
// ---------------------------------------------------------------------------
__global__ void __launch_bounds__(192) ln_proj_kernel(
    const float* __restrict__ x,
    const float* __restrict__ Wk, const float* __restrict__ Wq,
    const float* __restrict__ Wv,
    const float* __restrict__ gamma, const float* __restrict__ beta)
{
    extern __shared__ float2 xn2[];   // [512][17] float2 (row-pairs), 69632 B
    float* xnf = reinterpret_cast<float*>(xn2);

    const int tid  = threadIdx.x;
    const int warp = tid >> 5, lane = tid & 31;
    const int row0 = blockIdx.x * 32;

    // ---- LayerNorm: each warp handles rows warp, warp+6, ...
    for (int r = warp; r < 32; r += 6) {
        const float4* xr = reinterpret_cast<const float4*>(x + (size_t)(row0 + r) * Fn);
        float4 v[4];
        float s = 0.f, ss = 0.f;
#pragma unroll
        for (int k = 0; k < 4; k++) {
            v[k] = xr[lane + 32*k];
            s  += v[k].x + v[k].y + v[k].z + v[k].w;
            ss += v[k].x*v[k].x + v[k].y*v[k].y + v[k].z*v[k].z + v[k].w*v[k].w;
        }
#pragma unroll
        for (int o = 16; o; o >>= 1) {
            s  += __shfl_xor_sync(0xffffffffu, s,  o);
            ss += __shfl_xor_sync(0xffffffffu, ss, o);
        }
        const float mu   = s * (1.f/512.f);
        const float var  = ss * (1.f/512.f) - mu*mu;
        const float rstd = rsqrtf(var + 1e-5f);
        const int rp = r >> 1, h = r & 1;
#pragma unroll
        for (int k = 0; k < 4; k++) {
            const int q4i = lane + 32*k;
            float4 g4 = __ldg(reinterpret_cast<const float4*>(gamma) + q4i);
            float4 b4 = __ldg(reinterpret_cast<const float4*>(beta)  + q4i);
            float vv[4] = {v[k].x, v[k].y, v[k].z, v[k].w};
            float gg[4] = {g4.x, g4.y, g4.z, g4.w};
            float bb[4] = {b4.x, b4.y, b4.z, b4.w};
#pragma unroll
            for (int c = 0; c < 4; c++) {
                const int f = q4i*4 + c;
                xnf[(f*17 + rp)*2 + h] = (vv[c] - mu)*rstd*gg[c] + bb[c];
            }
        }
    }
    __syncthreads();

    // ---- Projections
    const int cg = tid % 48, rg = tid / 48;
    const int m  = cg >> 4,  jg = cg & 15;
    const float* W = (m == 0) ? Wk : ((m == 1) ? Wq : Wv);

    unsigned long long acc[4][4];
#pragma unroll
    for (int c = 0; c < 4; c++)
#pragma unroll
        for (int p = 0; p < 4; p++) acc[c][p] = 0ull;

    const unsigned long long* xb = reinterpret_cast<const unsigned long long*>(xn2);

#pragma unroll 4
    for (int f = 0; f < Fn; f++) {
        float4 w4 = __ldg(reinterpret_cast<const float4*>(W + f*Dn) + jg);
        unsigned long long x2[4];
        const unsigned long long* p2 = xb + f*17 + rg*4;
#pragma unroll
        for (int p = 0; p < 4; p++) x2[p] = p2[p];
        unsigned long long w2[4];
        w2[0] = pack2(w4.x, w4.x); w2[1] = pack2(w4.y, w4.y);
        w2[2] = pack2(w4.z, w4.z); w2[3] = pack2(w4.w, w4.w);
#pragma unroll
        for (int c = 0; c < 4; c++)
#pragma unroll
            for (int p = 0; p < 4; p++) fma2(acc[c][p], w2[c], x2[p]);
    }

    // Epilogue: unpack, relu (K,Q), row-sum normalize (K,Q), store.
    float vals[4][8];   // [col][row within group]
#pragma unroll
    for (int c = 0; c < 4; c++)
#pragma unroll
        for (int p = 0; p < 4; p++) {
            float2 u = unpack2(acc[c][p]);
            vals[c][2*p]   = u.x;
            vals[c][2*p+1] = u.y;
        }

    // relu'd copy for reduction (all lanes participate -> convergent shfl)
    float rv[4][8];
#pragma unroll
    for (int c = 0; c < 4; c++)
#pragma unroll
        for (int r = 0; r < 8; r++) rv[c][r] = fmaxf(vals[c][r], 0.f);

    float rs[8];
#pragma unroll
    for (int r = 0; r < 8; r++) {
        float s = rv[0][r] + rv[1][r] + rv[2][r] + rv[3][r];
#pragma unroll
        for (int o = 1; o < 16; o <<= 1) s += __shfl_xor_sync(0xffffffffu, s, o);
        rs[r] = 1.f / (1e-5f + s);
    }
    if (m < 2) {
#pragma unroll
        for (int c = 0; c < 4; c++)
#pragma unroll
            for (int r = 0; r < 8; r++) vals[c][r] = rv[c][r] * rs[r];
    }

    float* G = (m == 0) ? g_K : ((m == 1) ? g_Q : g_V);
#pragma unroll
    for (int r = 0; r < 8; r++) {
        const int row = row0 + rg*8 + r;
        float4 o4 = make_float4(vals[0][r], vals[1][r], vals[2][r], vals[3][r]);
        *reinterpret_cast<float4*>(G + (size_t)row*Dn + jg*4) = o4;
    }
}

// ---------------------------------------------------------------------------
// Kernel B: per-(batch,chunk) outer-product sums  S[b,c] = sum_t V_t (x) K_t
// grid (NC, B), 256 threads; thread owns 4i x 4j accumulators.
// ---------------------------------------------------------------------------
__global__ void __launch_bounds__(256) chunk_sum_kernel()
{
    __shared__ float Kc[TC*Dn], Vc[TC*Dn];
    const int c = blockIdx.x, b = blockIdx.y;
    const int base = (b*Tn + c*TC) * Dn;

    {
        const float4* Ks = reinterpret_cast<const float4*>(g_K + base);
        const float4* Vs = reinterpret_cast<const float4*>(g_V + base);
        float4* K4 = reinterpret_cast<float4*>(Kc);
        float4* V4 = reinterpret_cast<float4*>(Vc);
        for (int i = threadIdx.x; i < TC*Dn/4; i += 256) { K4[i] = Ks[i]; V4[i] = Vs[i]; }
    }
    __syncthreads();

    const int jg = threadIdx.x & 15, ig = threadIdx.x >> 4;
    float acc[4][4] = {};
#pragma unroll 4
    for (int t = 0; t < TC; t++) {
        float4 k4 = *reinterpret_cast<const float4*>(Kc + t*Dn + jg*4);
        float4 v4 = *reinterpret_cast<const float4*>(Vc + t*Dn + ig*4);
        float kk[4] = {k4.x, k4.y, k4.z, k4.w};
        float vv[4] = {v4.x, v4.y, v4.z, v4.w};
#pragma unroll
        for (int i = 0; i < 4; i++)
#pragma unroll
            for (int j = 0; j < 4; j++) acc[i][j] += vv[i]*kk[j];
    }

    float* S = g_S + (size_t)(b*NC + c) * (Dn*Dn);
#pragma unroll
    for (int i = 0; i < 4; i++)
        *reinterpret_cast<float4*>(S + (ig*4 + i)*Dn + jg*4) =
            make_float4(acc[i][0], acc[i][1], acc[i][2], acc[i][3]);
}

// ---------------------------------------------------------------------------
// Kernel D: per-(batch,chunk) scan: offset = state + sum of prior S chunks,
// then within-chunk running state, write state_seq + y.
// grid (NC, B), 256 threads; thread owns 4i x 4j state elements.
// ---------------------------------------------------------------------------
__global__ void __launch_bounds__(256) scan_kernel(
    const float* __restrict__ state, float* __restrict__ out)
{
    __shared__ float Kc[TC*Dn], Qc[TC*Dn], Vc[TC*Dn];
    __shared__ float ypart[2][16][Dn];

    const int c = blockIdx.x, b = blockIdx.y;
    const int jg = threadIdx.x & 15, ig = threadIdx.x >> 4;

    // Offset: initial state + exclusive-prefix of chunk sums
    float acc[4][4];
    {
        const float* st = state + (size_t)b * (Dn*Dn);
#pragma unroll
        for (int i = 0; i < 4; i++) {
            float4 s4 = __ldg(reinterpret_cast<const float4*>(st + (ig*4 + i)*Dn + jg*4));
            acc[i][0] = s4.x; acc[i][1] = s4.y; acc[i][2] = s4.z; acc[i][3] = s4.w;
        }
    }
    for (int cp = 0; cp < c; cp++) {
        const float* S = g_S + (size_t)(b*NC + cp) * (Dn*Dn);
#pragma unroll
        for (int i = 0; i < 4; i++) {
            float4 s4 = __ldg(reinterpret_cast<const float4*>(S + (ig*4 + i)*Dn + jg*4));
            acc[i][0] += s4.x; acc[i][1] += s4.y; acc[i][2] += s4.z; acc[i][3] += s4.w;
        }
    }

    {
        const int base = (b*Tn + c*TC) * Dn;
        const float4* Ks = reinterpret_cast<const float4*>(g_K + base);
        const float4* Qs = reinterpret_cast<const float4*>(g_Q + base);
        const float4* Vs = reinterpret_cast<const float4*>(g_V + base);
        float4* K4 = reinterpret_cast<float4*>(Kc);
        float4* Q4 = reinterpret_cast<float4*>(Qc);
        float4* V4 = reinterpret_cast<float4*>(Vc);
        for (int i = threadIdx.x; i < TC*Dn/4; i += 256) { K4[i] = Ks[i]; Q4[i] = Qs[i]; V4[i] = Vs[i]; }
    }
    __syncthreads();

    float* yout = out;                                  // [8192][64]
    float* sout = out + (size_t)ROWS * Dn;              // [8192][4096]

    for (int t = 0; t < TC; t++) {
        const int rglob = b*Tn + c*TC + t;
        float4 k4 = *reinterpret_cast<const float4*>(Kc + t*Dn + jg*4);
        float4 q4 = *reinterpret_cast<const float4*>(Qc + t*Dn + ig*4);
        float4 v4 = *reinterpret_cast<const float4*>(Vc + t*Dn + ig*4);
        float kk[4] = {k4.x, k4.y, k4.z, k4.w};
        float qq[4] = {q4.x, q4.y, q4.z, q4.w};
        float vv[4] = {v4.x, v4.y, v4.z, v4.w};

        float yp[4] = {0.f, 0.f, 0.f, 0.f};
#pragma unroll
        for (int i = 0; i < 4; i++) {
#pragma unroll
            for (int j = 0; j < 4; j++) {
                acc[i][j] += vv[i]*kk[j];
                yp[j]     += acc[i][j]*qq[i];
            }
            *reinterpret_cast<float4*>(sout + (size_t)rglob*(Dn*Dn) + (ig*4 + i)*Dn + jg*4) =
                make_float4(acc[i][0], acc[i][1], acc[i][2], acc[i][3]);
        }

        const int pb = t & 1;
        *reinterpret_cast<float4*>(&ypart[pb][ig][jg*4]) = make_float4(yp[0], yp[1], yp[2], yp[3]);
        __syncthreads();
        if (threadIdx.x < Dn) {
            float s = 0.f;
#pragma unroll
            for (int g = 0; g < 16; g++) s += ypart[pb][g][threadIdx.x];
            yout[(size_t)rglob*Dn + threadIdx.x] = s;
        }
    }
}

// ---------------------------------------------------------------------------
extern "C" void kernel_launch(void* const* d_in, const int* in_sizes, int n_in,
                              void* d_out, int out_size)
{
    const float* x     = (const float*)d_in[0];
    const float* state = (const float*)d_in[1];
    const float* Wk    = (const float*)d_in[2];
    const float* Wq    = (const float*)d_in[3];
    const float* Wv    = (const float*)d_in[4];
    const float* gamma = (const float*)d_in[5];
    const float* beta  = (const float*)d_in[6];
    float* out = (float*)d_out;

    const int smemA = 512 * 17 * 8;   // 69632 bytes
    cudaFuncSetAttribute(ln_proj_kernel, cudaFuncAttributeMaxDynamicSharedMemorySize, smemA);

    ln_proj_kernel<<<ROWS/32, 192, smemA>>>(x, Wk, Wq, Wv, gamma, beta);
    chunk_sum_kernel<<<dim3(NC, Bn), 256>>>();
    scan_kernel<<<dim3(NC, Bn), 256>>>(state, out);
}

// round 2
// speedup vs baseline: 1.0412x; 1.0412x over previous
#include <cuda_runtime.h>

// Problem constants
#define Bn 8
#define Tn 1024
#define Fn 512
#define Dn 64
#define ROWS (Bn*Tn)       // 8192
#define TC 32              // chunk length
#define NC (Tn/TC)         // 32 chunks

#define RPB 16             // rows per block (kernel A)
#define SU  9              // smem u64 stride per f (8 row-pairs + 1 pad)

// Scratch (no allocations allowed)
__device__ float g_K[ROWS*Dn];
__device__ float g_Q[ROWS*Dn];
__device__ float g_V[ROWS*Dn];
__device__ float g_S[Bn*NC*Dn*Dn];

__device__ __forceinline__ unsigned long long pack2(float a, float b){
    unsigned long long r;
    asm("mov.b64 %0, {%1, %2};" : "=l"(r) : "f"(a), "f"(b));
    return r;
}
__device__ __forceinline__ void fma2(unsigned long long &d, unsigned long long a, unsigned long long b){
    asm("fma.rn.f32x2 %0, %1, %2, %0;" : "+l"(d) : "l"(a), "l"(b));
}
__device__ __forceinline__ float2 unpack2(unsigned long long v){
    float2 u;
    asm("mov.b64 {%0, %1}, %2;" : "=f"(u.x), "=f"(u.y) : "l"(v));
    return u;
}

// ---------------------------------------------------------------------------
// Kernel A: LayerNorm + 3 projections (K,Q,V) + relu + sum-normalization
// 512 blocks x 192 threads; each block = 16 rows.
// smem: xn packed as f32x2 row-pairs, layout [f][rp] u64 with stride SU=9.
// Thread mapping: cg = tid%48 -> (matrix m = cg/16, col group jg = cg%16)
//                 rg = tid/48 (0..3) -> rows rg*4 .. rg*4+3 (2 row-pairs)
// ---------------------------------------------------------------------------
__global__ void __launch_bounds__(192) ln_proj_kernel(
    const float* __restrict__ x,
    const float* __restrict__ Wk, const float* __restrict__ Wq,
    const float* __restrict__ Wv,
    const float* __restrict__ gamma, const float* __restrict__ beta)
{
    extern __shared__ unsigned long long xb[];   // [512][SU] u64 = 36864 B
    float* xnf = reinterpret_cast<float*>(xb);

    const int tid  = threadIdx.x;
    const int warp = tid >> 5, lane = tid & 31;
    const int row0 = blockIdx.x * RPB;

    // ---- LayerNorm: each warp handles rows warp, warp+6, warp+12
    for (int r = warp; r < RPB; r += 6) {
        const float4* xr = reinterpret_cast<const float4*>(x + (size_t)(row0 + r) * Fn);
        float4 v[4];
        float s = 0.f, ss = 0.f;
#pragma unroll
        for (int k = 0; k < 4; k++) {
            v[k] = xr[lane + 32*k];
            s  += v[k].x + v[k].y + v[k].z + v[k].w;
            ss += v[k].x*v[k].x + v[k].y*v[k].y + v[k].z*v[k].z + v[k].w*v[k].w;
        }
#pragma unroll
        for (int o = 16; o; o >>= 1) {
            s  += __shfl_xor_sync(0xffffffffu, s,  o);
            ss += __shfl_xor_sync(0xffffffffu, ss, o);
        }
        const float mu   = s * (1.f/512.f);
        const float var  = ss * (1.f/512.f) - mu*mu;
        const float rstd = rsqrtf(var + 1e-5f);
        const int rp = r >> 1, h = r & 1;
#pragma unroll
        for (int k = 0; k < 4; k++) {
            const int q4i = lane + 32*k;
            float4 g4 = __ldg(reinterpret_cast<const float4*>(gamma) + q4i);
            float4 b4 = __ldg(reinterpret_cast<const float4*>(beta)  + q4i);
            float vv[4] = {v[k].x, v[k].y, v[k].z, v[k].w};
            float gg[4] = {g4.x, g4.y, g4.z, g4.w};
            float bb[4] = {b4.x, b4.y, b4.z, b4.w};
#pragma unroll
            for (int c = 0; c < 4; c++) {
                const int f = q4i*4 + c;
                xnf[(f*SU + rp)*2 + h] = (vv[c] - mu)*rstd*gg[c] + bb[c];
            }
        }
    }
    __syncthreads();

    // ---- Projections
    const int cg = tid % 48, rg = tid / 48;
    const int m  = cg >> 4,  jg = cg & 15;
    const float* W = (m == 0) ? Wk : ((m == 1) ? Wq : Wv);

    unsigned long long acc[4][2];
#pragma unroll
    for (int c = 0; c < 4; c++) { acc[c][0] = 0ull; acc[c][1] = 0ull; }

#pragma unroll 4
    for (int f = 0; f < Fn; f++) {
        float4 w4 = __ldg(reinterpret_cast<const float4*>(W + f*Dn) + jg);
        unsigned long long x2[2];
        x2[0] = xb[f*SU + rg*2];
        x2[1] = xb[f*SU + rg*2 + 1];
        unsigned long long w2[4];
        w2[0] = pack2(w4.x, w4.x); w2[1] = pack2(w4.y, w4.y);
        w2[2] = pack2(w4.z, w4.z); w2[3] = pack2(w4.w, w4.w);
#pragma unroll
        for (int c = 0; c < 4; c++) {
            fma2(acc[c][0], w2[c], x2[0]);
            fma2(acc[c][1], w2[c], x2[1]);
        }
    }

    // Epilogue: unpack, relu (K,Q), row-sum normalize (K,Q), store.
    float vals[4][4];   // [col][row within group of 4]
#pragma unroll
    for (int c = 0; c < 4; c++)
#pragma unroll
        for (int p = 0; p < 2; p++) {
            float2 u = unpack2(acc[c][p]);
            vals[c][2*p]   = u.x;
            vals[c][2*p+1] = u.y;
        }

    // relu'd copy for reduction (all lanes participate -> convergent shfl)
    float rv[4][4];
#pragma unroll
    for (int c = 0; c < 4; c++)
#pragma unroll
        for (int r = 0; r < 4; r++) rv[c][r] = fmaxf(vals[c][r], 0.f);

    float rs[4];
#pragma unroll
    for (int r = 0; r < 4; r++) {
        float s = rv[0][r] + rv[1][r] + rv[2][r] + rv[3][r];
#pragma unroll
        for (int o = 1; o < 16; o <<= 1) s += __shfl_xor_sync(0xffffffffu, s, o);
        rs[r] = 1.f / (1e-5f + s);
    }
    if (m < 2) {
#pragma unroll
        for (int c = 0; c < 4; c++)
#pragma unroll
            for (int r = 0; r < 4; r++) vals[c][r] = rv[c][r] * rs[r];
    }

    float* G = (m == 0) ? g_K : ((m == 1) ? g_Q : g_V);
#pragma unroll
    for (int r = 0; r < 4; r++) {
        const int row = row0 + rg*4 + r;
        float4 o4 = make_float4(vals[0][r], vals[1][r], vals[2][r], vals[3][r]);
        *reinterpret_cast<float4*>(G + (size_t)row*Dn + jg*4) = o4;
    }
}

// ---------------------------------------------------------------------------
// Kernel B: per-(batch,chunk) outer-product sums  S[b,c] = sum_t V_t (x) K_t
// grid (NC, B), 256 threads; thread owns 4i x 4j accumulators.
// ---------------------------------------------------------------------------
__global__ void __launch_bounds__(256) chunk_sum_kernel()
{
    __shared__ float Kc[TC*Dn], Vc[TC*Dn];
    const int c = blockIdx.x, b = blockIdx.y;
    const int base = (b*Tn + c*TC) * Dn;

    {
        const float4* Ks = reinterpret_cast<const float4*>(g_K + base);
        const float4* Vs = reinterpret_cast<const float4*>(g_V + base);
        float4* K4 = reinterpret_cast<float4*>(Kc);
        float4* V4 = reinterpret_cast<float4*>(Vc);
        for (int i = threadIdx.x; i < TC*Dn/4; i += 256) { K4[i] = Ks[i]; V4[i] = Vs[i]; }
    }
    __syncthreads();

    const int jg = threadIdx.x & 15, ig = threadIdx.x >> 4;
    float acc[4][4] = {};
#pragma unroll 4
    for (int t = 0; t < TC; t++) {
        float4 k4 = *reinterpret_cast<const float4*>(Kc + t*Dn + jg*4);
        float4 v4 = *reinterpret_cast<const float4*>(Vc + t*Dn + ig*4);
        float kk[4] = {k4.x, k4.y, k4.z, k4.w};
        float vv[4] = {v4.x, v4.y, v4.z, v4.w};
#pragma unroll
        for (int i = 0; i < 4; i++)
#pragma unroll
            for (int j = 0; j < 4; j++) acc[i][j] += vv[i]*kk[j];
    }

    float* S = g_S + (size_t)(b*NC + c) * (Dn*Dn);
#pragma unroll
    for (int i = 0; i < 4; i++)
        *reinterpret_cast<float4*>(S + (ig*4 + i)*Dn + jg*4) =
            make_float4(acc[i][0], acc[i][1], acc[i][2], acc[i][3]);
}

// ---------------------------------------------------------------------------
// Kernel D: per-(batch,chunk) scan: offset = state + sum of prior S chunks,
// then within-chunk running state, write state_seq + y.
// grid (NC, B), 256 threads; thread owns 4i x 4j state elements.
// ---------------------------------------------------------------------------
__global__ void __launch_bounds__(256) scan_kernel(
    const float* __restrict__ state, float* __restrict__ out)
{
    __shared__ float Kc[TC*Dn], Qc[TC*Dn], Vc[TC*Dn];
    __shared__ float ypart[2][16][Dn];

    const int c = blockIdx.x, b = blockIdx.y;
    const int jg = threadIdx.x & 15, ig = threadIdx.x >> 4;

    // Offset: initial state + exclusive-prefix of chunk sums
    float acc[4][4];
    {
        const float* st = state + (size_t)b * (Dn*Dn);
#pragma unroll
        for (int i = 0; i < 4; i++) {
            float4 s4 = __ldg(reinterpret_cast<const float4*>(st + (ig*4 + i)*Dn + jg*4));
            acc[i][0] = s4.x; acc[i][1] = s4.y; acc[i][2] = s4.z; acc[i][3] = s4.w;
        }
    }
    for (int cp = 0; cp < c; cp++) {
        const float* S = g_S + (size_t)(b*NC + cp) * (Dn*Dn);
#pragma unroll
        for (int i = 0; i < 4; i++) {
            float4 s4 = __ldg(reinterpret_cast<const float4*>(S + (ig*4 + i)*Dn + jg*4));
            acc[i][0] += s4.x; acc[i][1] += s4.y; acc[i][2] += s4.z; acc[i][3] += s4.w;
        }
    }

    {
        const int base = (b*Tn + c*TC) * Dn;
        const float4* Ks = reinterpret_cast<const float4*>(g_K + base);
        const float4* Qs = reinterpret_cast<const float4*>(g_Q + base);
        const float4* Vs = reinterpret_cast<const float4*>(g_V + base);
        float4* K4 = reinterpret_cast<float4*>(Kc);
        float4* Q4 = reinterpret_cast<float4*>(Qc);
        float4* V4 = reinterpret_cast<float4*>(Vc);
        for (int i = threadIdx.x; i < TC*Dn/4; i += 256) { K4[i] = Ks[i]; Q4[i] = Qs[i]; V4[i] = Vs[i]; }
    }
    __syncthreads();

    float* yout = out;                                  // [8192][64]
    float* sout = out + (size_t)ROWS * Dn;              // [8192][4096]

    for (int t = 0; t < TC; t++) {
        const int rglob = b*Tn + c*TC + t;
        float4 k4 = *reinterpret_cast<const float4*>(Kc + t*Dn + jg*4);
        float4 q4 = *reinterpret_cast<const float4*>(Qc + t*Dn + ig*4);
        float4 v4 = *reinterpret_cast<const float4*>(Vc + t*Dn + ig*4);
        float kk[4] = {k4.x, k4.y, k4.z, k4.w};
        float qq[4] = {q4.x, q4.y, q4.z, q4.w};
        float vv[4] = {v4.x, v4.y, v4.z, v4.w};

        float yp[4] = {0.f, 0.f, 0.f, 0.f};
#pragma unroll
        for (int i = 0; i < 4; i++) {
#pragma unroll
            for (int j = 0; j < 4; j++) {
                acc[i][j] += vv[i]*kk[j];
                yp[j]     += acc[i][j]*qq[i];
            }
            *reinterpret_cast<float4*>(sout + (size_t)rglob*(Dn*Dn) + (ig*4 + i)*Dn + jg*4) =
                make_float4(acc[i][0], acc[i][1], acc[i][2], acc[i][3]);
        }

        const int pb = t & 1;
        *reinterpret_cast<float4*>(&ypart[pb][ig][jg*4]) = make_float4(yp[0], yp[1], yp[2], yp[3]);
        __syncthreads();
        if (threadIdx.x < Dn) {
            float s = 0.f;
#pragma unroll
            for (int g = 0; g < 16; g++) s += ypart[pb][g][threadIdx.x];
            yout[(size_t)rglob*Dn + threadIdx.x] = s;
        }
    }
}

// ---------------------------------------------------------------------------
extern "C" void kernel_launch(void* const* d_in, const int* in_sizes, int n_in,
                              void* d_out, int out_size)
{
    const float* x     = (const float*)d_in[0];
    const float* state = (const float*)d_in[1];
    const float* Wk    = (const float*)d_in[2];
    const float* Wq    = (const float*)d_in[3];
    const float* Wv    = (const float*)d_in[4];
    const float* gamma = (const float*)d_in[5];
    const float* beta  = (const float*)d_in[6];
    float* out = (float*)d_out;

    const int smemA = Fn * SU * 8;   // 36864 bytes
    cudaFuncSetAttribute(ln_proj_kernel, cudaFuncAttributeMaxDynamicSharedMemorySize, smemA);

    ln_proj_kernel<<<ROWS/RPB, 192, smemA>>>(x, Wk, Wq, Wv, gamma, beta);
    chunk_sum_kernel<<<dim3(NC, Bn), 256>>>();
    scan_kernel<<<dim3(NC, Bn), 256>>>(state, out);
}